// round 12
// baseline (speedup 1.0000x reference)
#include <cuda_runtime.h>
#include <cuda_bf16.h>
#include <math.h>
#include <stdint.h>

#define BATCH 16
#define CCH 512
#define HW 1024
#define HEADS 8
#define HD 64
#define GROUPS 8
#define CPG 64
#define CEXP 0.1803368801111244f    // 0.125 * log2(e)

#define NGRP 4
#define BPG (BATCH / NGRP)          // 4 batches per group

// Scratch (no allocations allowed). All intermediates bf16.
__device__ __nv_bfloat16 g_xn[BATCH * CCH * HW];
__device__ __nv_bfloat16 g_qkv[BATCH * 3 * CCH * HW];
__device__ __nv_bfloat16 g_att[BATCH * CCH * HW];
__device__ __nv_bfloat16 g_wq[3 * CCH * CCH];
__device__ __nv_bfloat16 g_wo[CCH * CCH];

// ---------------------------------------------------------------------------
// helpers
// ---------------------------------------------------------------------------
__device__ __forceinline__ uint32_t pack_bf16(float lo, float hi) {
    uint32_t r;
    asm("cvt.rn.bf16x2.f32 %0, %1, %2;" : "=r"(r) : "f"(hi), "f"(lo));
    return r;
}

__device__ __forceinline__ uint32_t ex2_bf16x2(uint32_t x) {
    uint32_t y;
    asm("ex2.approx.ftz.bf16x2 %0, %1;" : "=r"(y) : "r"(x));
    return y;
}

__device__ __forceinline__ void mma_bf16(float* d, const uint32_t* a, const uint32_t* b) {
    asm volatile(
        "mma.sync.aligned.m16n8k16.row.col.f32.bf16.bf16.f32 "
        "{%0,%1,%2,%3}, {%4,%5,%6,%7}, {%8,%9}, {%0,%1,%2,%3};\n"
        : "+f"(d[0]), "+f"(d[1]), "+f"(d[2]), "+f"(d[3])
        : "r"(a[0]), "r"(a[1]), "r"(a[2]), "r"(a[3]), "r"(b[0]), "r"(b[1]));
}

__device__ __forceinline__ void ldsm4(uint32_t* r, uint32_t addr) {
    asm volatile("ldmatrix.sync.aligned.m8n8.x4.shared.b16 {%0,%1,%2,%3}, [%4];"
                 : "=r"(r[0]), "=r"(r[1]), "=r"(r[2]), "=r"(r[3]) : "r"(addr));
}
__device__ __forceinline__ void ldsm4t(uint32_t* r, uint32_t addr) {
    asm volatile("ldmatrix.sync.aligned.m8n8.x4.trans.shared.b16 {%0,%1,%2,%3}, [%4];"
                 : "=r"(r[0]), "=r"(r[1]), "=r"(r[2]), "=r"(r[3]) : "r"(addr));
}

__device__ __forceinline__ void cp16(uint32_t saddr, const void* gptr) {
    asm volatile("cp.async.cg.shared.global [%0], [%1], 16;\n" :: "r"(saddr), "l"(gptr));
}
#define CP_COMMIT()  asm volatile("cp.async.commit_group;\n" ::: "memory")
#define CP_WAIT0()   asm volatile("cp.async.wait_group 0;\n" ::: "memory")

// ---------------------------------------------------------------------------
// Kernel 0: weight fp32 -> bf16 conversion.
// ---------------------------------------------------------------------------
__global__ __launch_bounds__(256) void prep_weights(
    const float* __restrict__ wq, const float* __restrict__ wo) {
    int i = blockIdx.x * 256 + threadIdx.x;
    int stride = gridDim.x * 256;
    int nq = 3 * CCH * CCH / 4;
    for (int k = i; k < nq; k += stride) {
        float4 v = ((const float4*)wq)[k];
        ((uint2*)g_wq)[k] = make_uint2(pack_bf16(v.x, v.y), pack_bf16(v.z, v.w));
    }
    int no = CCH * CCH / 4;
    for (int k = i; k < no; k += stride) {
        float4 v = ((const float4*)wo)[k];
        ((uint2*)g_wo)[k] = make_uint2(pack_bf16(v.x, v.y), pack_bf16(v.z, v.w));
    }
}

// ---------------------------------------------------------------------------
// Kernel 1: GroupNorm (fp32 stats, bf16 out) for a batch group [b0, b0+BPG).
// ---------------------------------------------------------------------------
__global__ __launch_bounds__(256) void gn_kernel(
    const float* __restrict__ x, const float* __restrict__ gamma,
    const float* __restrict__ beta, int b0) {
    const int t = threadIdx.x;
    const int b = b0 + blockIdx.x / GROUPS, g = blockIdx.x % GROUPS;
    const float* xp = x + ((size_t)b * CCH + (size_t)g * CPG) * HW;
    __nv_bfloat16* op = g_xn + ((size_t)b * CCH + (size_t)g * CPG) * HW;
    const int n = CPG * HW;

    float s = 0.f, sq = 0.f;
    for (int i = t * 4; i < n; i += 1024) {
        float4 v = *(const float4*)(xp + i);
        s  += v.x + v.y + v.z + v.w;
        sq += v.x * v.x + v.y * v.y + v.z * v.z + v.w * v.w;
    }
    __shared__ float rs[256], rq[256];
    rs[t] = s; rq[t] = sq;
    __syncthreads();
    for (int o = 128; o > 0; o >>= 1) {
        if (t < o) { rs[t] += rs[t + o]; rq[t] += rq[t + o]; }
        __syncthreads();
    }
    __shared__ float s_mean, s_inv;
    if (t == 0) {
        float mean = rs[0] / (float)n;
        float var  = rq[0] / (float)n - mean * mean;
        s_mean = mean;
        s_inv  = rsqrtf(var + 1e-5f);
    }
    __syncthreads();
    const float mean = s_mean, inv = s_inv;
    for (int i = t * 4; i < n; i += 1024) {
        int ch = g * CPG + (i >> 10);
        float ga = gamma[ch] * inv;
        float be = beta[ch];
        float4 v = *(const float4*)(xp + i);
        uint2 p = make_uint2(
            pack_bf16((v.x - mean) * ga + be, (v.y - mean) * ga + be),
            pack_bf16((v.z - mean) * ga + be, (v.w - mean) * ga + be));
        *(uint2*)(op + i) = p;
    }
}

// ---------------------------------------------------------------------------
// Kernel 2/4: bf16 tensor-core batched GEMM (round-10 proven config).
//   BK=64, 2-stage double buffer, compile-time stage select, dynamic smem.
//   b0 = batch-group offset; blockIdx.z in [0, BPG).
// ---------------------------------------------------------------------------
#define GAS 72
#define GBS 136

template <int MT, bool RESID, bool SCALEK>
__global__ __launch_bounds__(256, 2) void gemm_bf(
    const __nv_bfloat16* __restrict__ W, const __nv_bfloat16* __restrict__ Xall,
    const float* __restrict__ bias, const float* __restrict__ resid,
    void* __restrict__ outAll, int M, int K, int b0) {
    const int N = HW;
    const int MROWS = 32 * MT;
    const int AS = MROWS * GAS;
    const int BS = 64 * GBS;
    const int bz = b0 + blockIdx.z;
    const __nv_bfloat16* X = Xall + (size_t)bz * K * N;
    const float* R = RESID ? (resid + (size_t)bz * M * N) : nullptr;

    extern __shared__ __nv_bfloat16 smg[];
    uint32_t base = (uint32_t)__cvta_generic_to_shared(smg);

    const int t = threadIdx.x;
    const int lane = t & 31, w = t >> 5;
    const int g = lane >> 2, t4 = lane & 3;
    const int l7 = lane & 7, b1 = (lane >> 3) & 1, b2 = (lane >> 4) & 1;
    const int wm = (w >> 2) * 16 * MT, wn = (w & 3) * 32;
    const int m0 = blockIdx.x * MROWS, n0 = blockIdx.y * 128;

    auto issue = [&](int k0, int st) {
        uint32_t sa = base + st * (AS + BS) * 2;
        uint32_t sb = sa + AS * 2;
        #pragma unroll
        for (int r = 0; r < MT; r++) {
            int c = t + r * 256;
            int row = c >> 3, cc = c & 7;
            cp16(sa + (row * GAS + cc * 8) * 2,
                 W + (size_t)(m0 + row) * K + k0 + cc * 8);
        }
        #pragma unroll
        for (int r = 0; r < 4; r++) {
            int c = t + r * 256;
            int row = c >> 4, cc = c & 15;
            cp16(sb + (row * GBS + cc * 8) * 2,
                 X + (size_t)(k0 + row) * N + n0 + cc * 8);
        }
        CP_COMMIT();
    };

    float acc[MT][4][4];
    #pragma unroll
    for (int i = 0; i < MT; i++)
        #pragma unroll
        for (int j = 0; j < 4; j++)
            #pragma unroll
            for (int r = 0; r < 4; r++) acc[i][j][r] = 0.f;

    const int nIter = K / 64;
    issue(0, 0);

    const int aoff = (b1 * 8 + l7) * GAS + b2 * 8;
    const int boff = (b1 * 8 + l7) * GBS + b2 * 8;

    #pragma unroll 2
    for (int it = 0; it < nIter; it++) {
        CP_WAIT0();
        __syncthreads();
        if (it + 1 < nIter) issue((it + 1) * 64, (it + 1) & 1);
        uint32_t sa = base + (it & 1) * (AS + BS) * 2;
        uint32_t sb = sa + AS * 2;

        #pragma unroll
        for (int s = 0; s < 4; s++) {
            uint32_t af[MT][4], bf[2][4];
            #pragma unroll
            for (int mt = 0; mt < MT; mt++)
                ldsm4(af[mt], sa + ((wm + 16 * mt) * GAS + s * 16 + aoff) * 2);
            #pragma unroll
            for (int ntp = 0; ntp < 2; ntp++)
                ldsm4t(bf[ntp], sb + (s * 16 * GBS + wn + 16 * ntp + boff) * 2);
            #pragma unroll
            for (int mt = 0; mt < MT; mt++)
                #pragma unroll
                for (int nt = 0; nt < 4; nt++)
                    mma_bf16(acc[mt][nt], af[mt], &bf[nt >> 1][(nt & 1) * 2]);
        }
    }

    const float kscale = (SCALEK && m0 >= CCH && m0 < 2 * CCH) ? CEXP : 1.0f;
    #pragma unroll
    for (int mt = 0; mt < MT; mt++) {
        int ma = m0 + wm + 16 * mt + g;
        int mb = ma + 8;
        float ba = __ldg(&bias[ma]), bb = __ldg(&bias[mb]);
        #pragma unroll
        for (int nt = 0; nt < 4; nt++) {
            int n = n0 + wn + 8 * nt + 2 * t4;
            float v0 = acc[mt][nt][0] + ba, v1 = acc[mt][nt][1] + ba;
            float v2 = acc[mt][nt][2] + bb, v3 = acc[mt][nt][3] + bb;
            if (RESID) {
                float* out = (float*)outAll + (size_t)bz * M * N;
                float2 ra = *(const float2*)&R[(size_t)ma * N + n];
                float2 rb = *(const float2*)&R[(size_t)mb * N + n];
                *(float2*)&out[(size_t)ma * N + n] = make_float2(v0 + ra.x, v1 + ra.y);
                *(float2*)&out[(size_t)mb * N + n] = make_float2(v2 + rb.x, v3 + rb.y);
            } else {
                if (SCALEK) { v0 *= kscale; v1 *= kscale; v2 *= kscale; v3 *= kscale; }
                __nv_bfloat16* out = (__nv_bfloat16*)outAll + (size_t)bz * M * N;
                *(uint32_t*)&out[(size_t)ma * N + n] = pack_bf16(v0, v1);
                *(uint32_t*)&out[(size_t)mb * N + n] = pack_bf16(v2, v3);
            }
        }
    }
}

// ---------------------------------------------------------------------------
// Kernel 3: bf16 flash attention (round-10 proven). bh0 = group offset.
// ---------------------------------------------------------------------------
#define BQ 128
#define AQS 136
#define AKS 72
#define OFF_K 8704
#define OFF_V (8704 + 2 * 4608)
#define ATT_ELTS (17920 + 2 * 4608)

__global__ __launch_bounds__(256, 2) void attn_bf(int bh0) {
    extern __shared__ __nv_bfloat16 smb[];
    uint32_t base = (uint32_t)__cvta_generic_to_shared(smb);

    const int t = threadIdx.x;
    const int lane = t & 31, w = t >> 5;
    const int g = lane >> 2, t4 = lane & 3;
    const int l7 = lane & 7, b1 = (lane >> 3) & 1, b2 = (lane >> 4) & 1;
    const int q2 = lane >> 3;
    const int iw = w * 16;
    const int bh = bh0 + blockIdx.y;
    const int b = bh >> 3, h = bh & 7;
    const int i0g = blockIdx.x * BQ;

    const __nv_bfloat16* qb = g_qkv + ((size_t)b * 3 * CCH + (size_t)h * HD) * HW;
    const __nv_bfloat16* kb = qb + (size_t)CCH * HW;
    const __nv_bfloat16* vb = qb + (size_t)2 * CCH * HW;

    #pragma unroll
    for (int r = 0; r < 4; r++) {
        int c = t + r * 256;
        int row = c >> 4, cc = c & 15;
        cp16(base + (row * AQS + cc * 8) * 2, qb + (size_t)row * HW + i0g + cc * 8);
    }

    auto issueKV = [&](int j0, int st) {
        uint32_t ks = base + (OFF_K + st * 4608) * 2;
        uint32_t vs = base + (OFF_V + st * 4608) * 2;
        #pragma unroll
        for (int r = 0; r < 2; r++) {
            int c = t + r * 256;
            int row = c >> 3, cc = c & 7;
            cp16(ks + (row * AKS + cc * 8) * 2, kb + (size_t)row * HW + j0 + cc * 8);
            cp16(vs + (row * AKS + cc * 8) * 2, vb + (size_t)row * HW + j0 + cc * 8);
        }
        CP_COMMIT();
    };
    issueKV(0, 0);

    float o[8][4];
    #pragma unroll
    for (int dt = 0; dt < 8; dt++)
        #pragma unroll
        for (int r = 0; r < 4; r++) o[dt][r] = 0.f;
    float lacc[4] = {0.f, 0.f, 0.f, 0.f};
    const uint32_t onesb[2] = {0x3F803F80u, 0x3F803F80u};

    uint32_t qf[4][4];
    const int qoff = (b2 * 8 + l7) * AQS + iw + b1 * 8;
    const int koff = (b1 * 8 + l7) * AKS + b2 * 8;
    const int voff = l7 * AKS + q2 * 8;

    #pragma unroll 2
    for (int jt = 0; jt < 16; jt++) {
        CP_WAIT0();
        __syncthreads();
        if (jt + 1 < 16) issueKV((jt + 1) * 64, (jt + 1) & 1);

        if (jt == 0) {
            #pragma unroll
            for (int u = 0; u < 4; u++)
                ldsm4t(qf[u], base + (u * 16 * AQS + qoff) * 2);
        }
        uint32_t ksb = base + (OFF_K + (jt & 1) * 4608) * 2;
        uint32_t vsb = base + (OFF_V + (jt & 1) * 4608) * 2;

        float s[8][4];
        #pragma unroll
        for (int nt = 0; nt < 8; nt++)
            #pragma unroll
            for (int r = 0; r < 4; r++) s[nt][r] = 0.f;

        #pragma unroll
        for (int u = 0; u < 4; u++) {
            uint32_t kf[4][4];
            #pragma unroll
            for (int ntp = 0; ntp < 4; ntp++)
                ldsm4t(kf[ntp], ksb + (u * 16 * AKS + 16 * ntp + koff) * 2);
            #pragma unroll
            for (int nt = 0; nt < 8; nt++)
                mma_bf16(s[nt], qf[u], &kf[nt >> 1][(nt & 1) * 2]);
        }

        uint32_t pa[4][4];
        #pragma unroll
        for (int nt = 0; nt < 8; nt++) {
            pa[nt >> 1][(nt & 1) * 2]     = ex2_bf16x2(pack_bf16(s[nt][0], s[nt][1]));
            pa[nt >> 1][(nt & 1) * 2 + 1] = ex2_bf16x2(pack_bf16(s[nt][2], s[nt][3]));
        }

        #pragma unroll
        for (int u = 0; u < 4; u++)
            mma_bf16(lacc, pa[u], onesb);

        #pragma unroll
        for (int up = 0; up < 2; up++) {
            #pragma unroll
            for (int dt = 0; dt < 8; dt++) {
                uint32_t vf[4];
                ldsm4(vf, vsb + (dt * 8 * AKS + up * 32 + voff) * 2);
                mma_bf16(o[dt], pa[2 * up],     &vf[0]);
                mma_bf16(o[dt], pa[2 * up + 1], &vf[2]);
            }
        }
    }

    float inv_lo = 1.0f / lacc[0], inv_hi = 1.0f / lacc[2];

    __nv_bfloat16* ob = g_att + ((size_t)b * CCH + (size_t)h * HD) * HW;
    const int i_lo = i0g + iw + g, i_hi = i_lo + 8;
    #pragma unroll
    for (int dt = 0; dt < 8; dt++) {
        int d = dt * 8 + 2 * t4;
        ob[(size_t)d * HW + i_lo]       = __float2bfloat16_rn(o[dt][0] * inv_lo);
        ob[(size_t)(d + 1) * HW + i_lo] = __float2bfloat16_rn(o[dt][1] * inv_lo);
        ob[(size_t)d * HW + i_hi]       = __float2bfloat16_rn(o[dt][2] * inv_hi);
        ob[(size_t)(d + 1) * HW + i_hi] = __float2bfloat16_rn(o[dt][3] * inv_hi);
    }
}

// ---------------------------------------------------------------------------
// Stream/event pool: host-side resources created once (not device memory).
// ---------------------------------------------------------------------------
struct StreamPool {
    cudaStream_t s[2];
    cudaEvent_t root, done[2];
    StreamPool() {
        for (int i = 0; i < 2; i++)
            cudaStreamCreateWithFlags(&s[i], cudaStreamNonBlocking);
        cudaEventCreateWithFlags(&root, cudaEventDisableTiming);
        for (int i = 0; i < 2; i++)
            cudaEventCreateWithFlags(&done[i], cudaEventDisableTiming);
    }
};
static StreamPool& pool() { static StreamPool P; return P; }

extern "C" void kernel_launch(void* const* d_in, const int* in_sizes, int n_in,
                              void* d_out, int out_size) {
    const float* x     = (const float*)d_in[0];
    const float* gamma = (const float*)d_in[1];
    const float* beta  = (const float*)d_in[2];
    const float* w_qkv = (const float*)d_in[3];
    const float* b_qkv = (const float*)d_in[4];
    const float* w_out = (const float*)d_in[5];
    const float* b_out = (const float*)d_in[6];

    __nv_bfloat16 *xn, *qkv, *att, *wq, *wo;
    cudaGetSymbolAddress((void**)&xn,  g_xn);
    cudaGetSymbolAddress((void**)&qkv, g_qkv);
    cudaGetSymbolAddress((void**)&att, g_att);
    cudaGetSymbolAddress((void**)&wq,  g_wq);
    cudaGetSymbolAddress((void**)&wo,  g_wo);

    const int qkv_smem = 2 * (128 * GAS + 64 * GBS) * 2;   // 71680 B
    const int op_smem  = 2 * (64 * GAS + 64 * GBS) * 2;    // 53248 B
    const int attn_smem = ATT_ELTS * 2;                    // 54272 B
    cudaFuncSetAttribute(gemm_bf<4, false, true>,
                         cudaFuncAttributeMaxDynamicSharedMemorySize, qkv_smem);
    cudaFuncSetAttribute(gemm_bf<2, true, false>,
                         cudaFuncAttributeMaxDynamicSharedMemorySize, op_smem);
    cudaFuncSetAttribute(attn_bf, cudaFuncAttributeMaxDynamicSharedMemorySize,
                         attn_smem);

    StreamPool& P = pool();

    // 0) weight conversion on the launch stream, then fork.
    prep_weights<<<128, 256>>>(w_qkv, w_out);
    cudaEventRecord(P.root, 0);
    cudaStreamWaitEvent(P.s[0], P.root, 0);
    cudaStreamWaitEvent(P.s[1], P.root, 0);

    // 1) pipelined batch groups across 2 streams.
    for (int g = 0; g < NGRP; g++) {
        cudaStream_t st = P.s[g & 1];
        const int b0 = g * BPG;
        gn_kernel<<<BPG * GROUPS, 256, 0, st>>>(x, gamma, beta, b0);
        gemm_bf<4, false, true><<<dim3(12, 8, BPG), 256, qkv_smem, st>>>(
            wq, xn, b_qkv, nullptr, qkv, 3 * CCH, CCH, b0);
        attn_bf<<<dim3(HW / BQ, BPG * HEADS), 256, attn_smem, st>>>(b0 * HEADS);
        gemm_bf<2, true, false><<<dim3(8, 8, BPG), 256, op_smem, st>>>(
            wo, att, b_out, x, d_out, CCH, CCH, b0);
    }

    // 2) join back to the launch stream.
    cudaEventRecord(P.done[0], P.s[0]);
    cudaEventRecord(P.done[1], P.s[1]);
    cudaStreamWaitEvent(0, P.done[0], 0);
    cudaStreamWaitEvent(0, P.done[1], 0);
}

// round 13
// speedup vs baseline: 1.1521x; 1.1521x over previous
#include <cuda_runtime.h>
#include <cuda_bf16.h>
#include <math.h>
#include <stdint.h>

#define BATCH 16
#define CCH 512
#define HW 1024
#define HEADS 8
#define HD 64
#define GROUPS 8
#define CPG 64
#define CEXP 0.1803368801111244f    // 0.125 * log2(e)

// Scratch (no allocations allowed). All intermediates bf16.
__device__ __nv_bfloat16 g_xn[BATCH * CCH * HW];
__device__ __nv_bfloat16 g_qkv[BATCH * 3 * CCH * HW];
__device__ __nv_bfloat16 g_att[BATCH * CCH * HW];
__device__ __nv_bfloat16 g_wq[3 * CCH * CCH];
__device__ __nv_bfloat16 g_wo[CCH * CCH];

// ---------------------------------------------------------------------------
// helpers
// ---------------------------------------------------------------------------
__device__ __forceinline__ uint32_t pack_bf16(float lo, float hi) {
    uint32_t r;
    asm("cvt.rn.bf16x2.f32 %0, %1, %2;" : "=r"(r) : "f"(hi), "f"(lo));
    return r;
}

__device__ __forceinline__ uint32_t ex2_bf16x2(uint32_t x) {
    uint32_t y;
    asm("ex2.approx.ftz.bf16x2 %0, %1;" : "=r"(y) : "r"(x));
    return y;
}

__device__ __forceinline__ void mma_bf16(float* d, const uint32_t* a, const uint32_t* b) {
    asm volatile(
        "mma.sync.aligned.m16n8k16.row.col.f32.bf16.bf16.f32 "
        "{%0,%1,%2,%3}, {%4,%5,%6,%7}, {%8,%9}, {%0,%1,%2,%3};\n"
        : "+f"(d[0]), "+f"(d[1]), "+f"(d[2]), "+f"(d[3])
        : "r"(a[0]), "r"(a[1]), "r"(a[2]), "r"(a[3]), "r"(b[0]), "r"(b[1]));
}

__device__ __forceinline__ void ldsm4(uint32_t* r, uint32_t addr) {
    asm volatile("ldmatrix.sync.aligned.m8n8.x4.shared.b16 {%0,%1,%2,%3}, [%4];"
                 : "=r"(r[0]), "=r"(r[1]), "=r"(r[2]), "=r"(r[3]) : "r"(addr));
}
__device__ __forceinline__ void ldsm4t(uint32_t* r, uint32_t addr) {
    asm volatile("ldmatrix.sync.aligned.m8n8.x4.trans.shared.b16 {%0,%1,%2,%3}, [%4];"
                 : "=r"(r[0]), "=r"(r[1]), "=r"(r[2]), "=r"(r[3]) : "r"(addr));
}

__device__ __forceinline__ void cp16(uint32_t saddr, const void* gptr) {
    asm volatile("cp.async.cg.shared.global [%0], [%1], 16;\n" :: "r"(saddr), "l"(gptr));
}
#define CP_COMMIT()  asm volatile("cp.async.commit_group;\n" ::: "memory")
#define CP_WAIT0()   asm volatile("cp.async.wait_group 0;\n" ::: "memory")
#define CP_WAIT1()   asm volatile("cp.async.wait_group 1;\n" ::: "memory")

// ---------------------------------------------------------------------------
// Kernel 1: fused GroupNorm (blocks 0..127) + weight bf16 convert (128..255).
// ---------------------------------------------------------------------------
__global__ __launch_bounds__(256) void gn_prep_kernel(
    const float* __restrict__ x, const float* __restrict__ gamma,
    const float* __restrict__ beta,
    const float* __restrict__ wq, const float* __restrict__ wo) {
    const int t = threadIdx.x;
    if (blockIdx.x >= BATCH * GROUPS) {
        int i = (blockIdx.x - BATCH * GROUPS) * 256 + t;
        int stride = 128 * 256;
        int nq = 3 * CCH * CCH / 4;
        for (int k = i; k < nq; k += stride) {
            float4 v = ((const float4*)wq)[k];
            ((uint2*)g_wq)[k] = make_uint2(pack_bf16(v.x, v.y), pack_bf16(v.z, v.w));
        }
        int no = CCH * CCH / 4;
        for (int k = i; k < no; k += stride) {
            float4 v = ((const float4*)wo)[k];
            ((uint2*)g_wo)[k] = make_uint2(pack_bf16(v.x, v.y), pack_bf16(v.z, v.w));
        }
        return;
    }
    const int b = blockIdx.x / GROUPS, g = blockIdx.x % GROUPS;
    const float* xp = x + ((size_t)b * CCH + (size_t)g * CPG) * HW;
    __nv_bfloat16* op = g_xn + ((size_t)b * CCH + (size_t)g * CPG) * HW;
    const int n = CPG * HW;

    float s = 0.f, sq = 0.f;
    for (int i = t * 4; i < n; i += 1024) {
        float4 v = *(const float4*)(xp + i);
        s  += v.x + v.y + v.z + v.w;
        sq += v.x * v.x + v.y * v.y + v.z * v.z + v.w * v.w;
    }
    __shared__ float rs[256], rq[256];
    rs[t] = s; rq[t] = sq;
    __syncthreads();
    for (int o = 128; o > 0; o >>= 1) {
        if (t < o) { rs[t] += rs[t + o]; rq[t] += rq[t + o]; }
        __syncthreads();
    }
    __shared__ float s_mean, s_inv;
    if (t == 0) {
        float mean = rs[0] / (float)n;
        float var  = rq[0] / (float)n - mean * mean;
        s_mean = mean;
        s_inv  = rsqrtf(var + 1e-5f);
    }
    __syncthreads();
    const float mean = s_mean, inv = s_inv;
    for (int i = t * 4; i < n; i += 1024) {
        int ch = g * CPG + (i >> 10);
        float ga = gamma[ch] * inv;
        float be = beta[ch];
        float4 v = *(const float4*)(xp + i);
        uint2 p = make_uint2(
            pack_bf16((v.x - mean) * ga + be, (v.y - mean) * ga + be),
            pack_bf16((v.z - mean) * ga + be, (v.w - mean) * ga + be));
        *(uint2*)(op + i) = p;
    }
}

// ---------------------------------------------------------------------------
// Kernel 2/4: bf16 tensor-core batched GEMM. K=512 fixed -> 8 fully-unrolled
//   BK=64 iterations, 3-stage ring with compile-time stage indices,
//   prefetch depth 2 (wait_group 1 until the final iteration).
// ---------------------------------------------------------------------------
#define GAS 72
#define GBS 136

template <int MT, bool RESID, bool SCALEK>
__global__ __launch_bounds__(256, 2) void gemm_bf(
    const __nv_bfloat16* __restrict__ W, const __nv_bfloat16* __restrict__ Xall,
    const float* __restrict__ bias, const float* __restrict__ resid,
    void* __restrict__ outAll, int M) {
    const int N = HW;
    const int K = CCH;                    // 512, fixed
    const int MROWS = 32 * MT;
    const int AS = MROWS * GAS;
    const int BS = 64 * GBS;
    const int bz = blockIdx.z;
    const __nv_bfloat16* X = Xall + (size_t)bz * K * N;
    const float* R = RESID ? (resid + (size_t)bz * M * N) : nullptr;

    extern __shared__ __nv_bfloat16 smg[];
    uint32_t base = (uint32_t)__cvta_generic_to_shared(smg);

    const int t = threadIdx.x;
    const int lane = t & 31, w = t >> 5;
    const int g = lane >> 2, t4 = lane & 3;
    const int l7 = lane & 7, b1 = (lane >> 3) & 1, b2 = (lane >> 4) & 1;
    const int wm = (w >> 2) * 16 * MT, wn = (w & 3) * 32;
    const int m0 = blockIdx.x * MROWS, n0 = blockIdx.y * 128;

    auto issue = [&](int k0, int st) {
        uint32_t sa = base + st * (AS + BS) * 2;
        uint32_t sb = sa + AS * 2;
        #pragma unroll
        for (int r = 0; r < MT; r++) {
            int c = t + r * 256;
            int row = c >> 3, cc = c & 7;
            cp16(sa + (row * GAS + cc * 8) * 2,
                 W + (size_t)(m0 + row) * K + k0 + cc * 8);
        }
        #pragma unroll
        for (int r = 0; r < 4; r++) {
            int c = t + r * 256;
            int row = c >> 4, cc = c & 15;
            cp16(sb + (row * GBS + cc * 8) * 2,
                 X + (size_t)(k0 + row) * N + n0 + cc * 8);
        }
        CP_COMMIT();
    };

    float acc[MT][4][4];
    #pragma unroll
    for (int i = 0; i < MT; i++)
        #pragma unroll
        for (int j = 0; j < 4; j++)
            #pragma unroll
            for (int r = 0; r < 4; r++) acc[i][j][r] = 0.f;

    issue(0, 0);
    issue(64, 1);

    const int aoff = (b1 * 8 + l7) * GAS + b2 * 8;
    const int boff = (b1 * 8 + l7) * GBS + b2 * 8;

    #pragma unroll
    for (int it = 0; it < 8; it++) {
        if (it == 7) { CP_WAIT0(); } else { CP_WAIT1(); }
        __syncthreads();
        if (it + 2 < 8) issue((it + 2) * 64, (it + 2) % 3);
        const int st = it % 3;                       // compile-time (full unroll)
        uint32_t sa = base + st * (AS + BS) * 2;
        uint32_t sb = sa + AS * 2;

        #pragma unroll
        for (int s = 0; s < 4; s++) {
            uint32_t af[MT][4], bf[2][4];
            #pragma unroll
            for (int mt = 0; mt < MT; mt++)
                ldsm4(af[mt], sa + ((wm + 16 * mt) * GAS + s * 16 + aoff) * 2);
            #pragma unroll
            for (int ntp = 0; ntp < 2; ntp++)
                ldsm4t(bf[ntp], sb + (s * 16 * GBS + wn + 16 * ntp + boff) * 2);
            #pragma unroll
            for (int mt = 0; mt < MT; mt++)
                #pragma unroll
                for (int nt = 0; nt < 4; nt++)
                    mma_bf16(acc[mt][nt], af[mt], &bf[nt >> 1][(nt & 1) * 2]);
        }
    }

    const float kscale = (SCALEK && m0 >= CCH && m0 < 2 * CCH) ? CEXP : 1.0f;
    #pragma unroll
    for (int mt = 0; mt < MT; mt++) {
        int ma = m0 + wm + 16 * mt + g;
        int mb = ma + 8;
        float ba = __ldg(&bias[ma]), bb = __ldg(&bias[mb]);
        #pragma unroll
        for (int nt = 0; nt < 4; nt++) {
            int n = n0 + wn + 8 * nt + 2 * t4;
            float v0 = acc[mt][nt][0] + ba, v1 = acc[mt][nt][1] + ba;
            float v2 = acc[mt][nt][2] + bb, v3 = acc[mt][nt][3] + bb;
            if (RESID) {
                float* out = (float*)outAll + (size_t)bz * M * N;
                float2 ra = *(const float2*)&R[(size_t)ma * N + n];
                float2 rb = *(const float2*)&R[(size_t)mb * N + n];
                *(float2*)&out[(size_t)ma * N + n] = make_float2(v0 + ra.x, v1 + ra.y);
                *(float2*)&out[(size_t)mb * N + n] = make_float2(v2 + rb.x, v3 + rb.y);
            } else {
                if (SCALEK) { v0 *= kscale; v1 *= kscale; v2 *= kscale; v3 *= kscale; }
                __nv_bfloat16* out = (__nv_bfloat16*)outAll + (size_t)bz * M * N;
                *(uint32_t*)&out[(size_t)ma * N + n] = pack_bf16(v0, v1);
                *(uint32_t*)&out[(size_t)mb * N + n] = pack_bf16(v2, v3);
            }
        }
    }
}

// ---------------------------------------------------------------------------
// Kernel 3: bf16 flash attention. 4-stage KV ring ((jt&3) indexing),
//   prefetch depth 2 (wait_group 1; wait_group 0 on the last iteration).
//   K pre-scaled by 0.125*log2e -> P = 2^s via one ex2.bf16x2 per pair.
//   No online max; l via all-ones MMA on P fragments.
// ---------------------------------------------------------------------------
#define BQ 128
#define AQS 136
#define AKS 72
#define OFF_K 8704                       // after Q (64*136)
#define OFF_V (8704 + 4 * 4608)          // 27136
#define ATT_ELTS (27136 + 4 * 4608)      // 45568 bf16 = 91136 B

__global__ __launch_bounds__(256, 2) void attn_bf() {
    extern __shared__ __nv_bfloat16 smb[];
    uint32_t base = (uint32_t)__cvta_generic_to_shared(smb);

    const int t = threadIdx.x;
    const int lane = t & 31, w = t >> 5;
    const int g = lane >> 2, t4 = lane & 3;
    const int l7 = lane & 7, b1 = (lane >> 3) & 1, b2 = (lane >> 4) & 1;
    const int q2 = lane >> 3;
    const int iw = w * 16;
    const int bh = blockIdx.y;
    const int b = bh >> 3, h = bh & 7;
    const int i0g = blockIdx.x * BQ;

    const __nv_bfloat16* qb = g_qkv + ((size_t)b * 3 * CCH + (size_t)h * HD) * HW;
    const __nv_bfloat16* kb = qb + (size_t)CCH * HW;
    const __nv_bfloat16* vb = qb + (size_t)2 * CCH * HW;

    // Q tile -> smem [d][i] (committed with KV stage 0's group)
    #pragma unroll
    for (int r = 0; r < 4; r++) {
        int c = t + r * 256;
        int row = c >> 4, cc = c & 15;
        cp16(base + (row * AQS + cc * 8) * 2, qb + (size_t)row * HW + i0g + cc * 8);
    }

    auto issueKV = [&](int j0, int st) {
        uint32_t ks = base + (OFF_K + st * 4608) * 2;
        uint32_t vs = base + (OFF_V + st * 4608) * 2;
        #pragma unroll
        for (int r = 0; r < 2; r++) {
            int c = t + r * 256;
            int row = c >> 3, cc = c & 7;
            cp16(ks + (row * AKS + cc * 8) * 2, kb + (size_t)row * HW + j0 + cc * 8);
            cp16(vs + (row * AKS + cc * 8) * 2, vb + (size_t)row * HW + j0 + cc * 8);
        }
        CP_COMMIT();
    };
    issueKV(0, 0);    // includes Q chunks
    issueKV(64, 1);

    float o[8][4];
    #pragma unroll
    for (int dt = 0; dt < 8; dt++)
        #pragma unroll
        for (int r = 0; r < 4; r++) o[dt][r] = 0.f;
    float lacc[4] = {0.f, 0.f, 0.f, 0.f};
    const uint32_t onesb[2] = {0x3F803F80u, 0x3F803F80u};

    uint32_t qf[4][4];
    const int qoff = (b2 * 8 + l7) * AQS + iw + b1 * 8;
    const int koff = (b1 * 8 + l7) * AKS + b2 * 8;
    const int voff = l7 * AKS + q2 * 8;

    #pragma unroll 4
    for (int jt = 0; jt < 16; jt++) {
        if (jt == 15) { CP_WAIT0(); } else { CP_WAIT1(); }
        __syncthreads();
        if (jt + 2 < 16) issueKV((jt + 2) * 64, (jt + 2) & 3);

        if (jt == 0) {
            #pragma unroll
            for (int u = 0; u < 4; u++)
                ldsm4t(qf[u], base + (u * 16 * AQS + qoff) * 2);
        }
        uint32_t ksb = base + (OFF_K + (jt & 3) * 4608) * 2;
        uint32_t vsb = base + (OFF_V + (jt & 3) * 4608) * 2;

        // ---- S = Q K' ----
        float s[8][4];
        #pragma unroll
        for (int nt = 0; nt < 8; nt++)
            #pragma unroll
            for (int r = 0; r < 4; r++) s[nt][r] = 0.f;

        #pragma unroll
        for (int u = 0; u < 4; u++) {
            uint32_t kf[4][4];
            #pragma unroll
            for (int ntp = 0; ntp < 4; ntp++)
                ldsm4t(kf[ntp], ksb + (u * 16 * AKS + 16 * ntp + koff) * 2);
            #pragma unroll
            for (int nt = 0; nt < 8; nt++)
                mma_bf16(s[nt], qf[u], &kf[nt >> 1][(nt & 1) * 2]);
        }

        // ---- P = 2^s ----
        uint32_t pa[4][4];
        #pragma unroll
        for (int nt = 0; nt < 8; nt++) {
            pa[nt >> 1][(nt & 1) * 2]     = ex2_bf16x2(pack_bf16(s[nt][0], s[nt][1]));
            pa[nt >> 1][(nt & 1) * 2 + 1] = ex2_bf16x2(pack_bf16(s[nt][2], s[nt][3]));
        }

        // ---- l += P * ones ----
        #pragma unroll
        for (int u = 0; u < 4; u++)
            mma_bf16(lacc, pa[u], onesb);

        // ---- O += P V^T ----
        #pragma unroll
        for (int up = 0; up < 2; up++) {
            #pragma unroll
            for (int dt = 0; dt < 8; dt++) {
                uint32_t vf[4];
                ldsm4(vf, vsb + (dt * 8 * AKS + up * 32 + voff) * 2);
                mma_bf16(o[dt], pa[2 * up],     &vf[0]);
                mma_bf16(o[dt], pa[2 * up + 1], &vf[2]);
            }
        }
    }

    float inv_lo = 1.0f / lacc[0], inv_hi = 1.0f / lacc[2];

    __nv_bfloat16* ob = g_att + ((size_t)b * CCH + (size_t)h * HD) * HW;
    const int i_lo = i0g + iw + g, i_hi = i_lo + 8;
    #pragma unroll
    for (int dt = 0; dt < 8; dt++) {
        int d = dt * 8 + 2 * t4;
        ob[(size_t)d * HW + i_lo]       = __float2bfloat16_rn(o[dt][0] * inv_lo);
        ob[(size_t)(d + 1) * HW + i_lo] = __float2bfloat16_rn(o[dt][1] * inv_lo);
        ob[(size_t)d * HW + i_hi]       = __float2bfloat16_rn(o[dt][2] * inv_hi);
        ob[(size_t)(d + 1) * HW + i_hi] = __float2bfloat16_rn(o[dt][3] * inv_hi);
    }
}

// ---------------------------------------------------------------------------

extern "C" void kernel_launch(void* const* d_in, const int* in_sizes, int n_in,
                              void* d_out, int out_size) {
    const float* x     = (const float*)d_in[0];
    const float* gamma = (const float*)d_in[1];
    const float* beta  = (const float*)d_in[2];
    const float* w_qkv = (const float*)d_in[3];
    const float* b_qkv = (const float*)d_in[4];
    const float* w_out = (const float*)d_in[5];
    const float* b_out = (const float*)d_in[6];

    __nv_bfloat16 *xn, *qkv, *att, *wq, *wo;
    cudaGetSymbolAddress((void**)&xn,  g_xn);
    cudaGetSymbolAddress((void**)&qkv, g_qkv);
    cudaGetSymbolAddress((void**)&att, g_att);
    cudaGetSymbolAddress((void**)&wq,  g_wq);
    cudaGetSymbolAddress((void**)&wo,  g_wo);

    // 1) fused GroupNorm + weight conversion
    gn_prep_kernel<<<BATCH * GROUPS + 128, 256>>>(x, gamma, beta, w_qkv, w_out);

    // 2) QKV projection: MT=4, 3-stage ring. smem 107520 B.
    const int qkv_smem = 3 * (128 * GAS + 64 * GBS) * 2;
    cudaFuncSetAttribute(gemm_bf<4, false, true>,
                         cudaFuncAttributeMaxDynamicSharedMemorySize, qkv_smem);
    gemm_bf<4, false, true><<<dim3(12, 8, BATCH), 256, qkv_smem>>>(
        wq, xn, b_qkv, nullptr, qkv, 3 * CCH);

    // 3) Attention: 4-stage KV ring. smem 91136 B.
    const int attn_smem = ATT_ELTS * 2;
    cudaFuncSetAttribute(attn_bf, cudaFuncAttributeMaxDynamicSharedMemorySize,
                         attn_smem);
    attn_bf<<<dim3(HW / BQ, BATCH * HEADS), 256, attn_smem>>>();

    // 4) Output projection + residual: MT=2, 3-stage ring. smem 79872 B.
    const int op_smem = 3 * (64 * GAS + 64 * GBS) * 2;
    cudaFuncSetAttribute(gemm_bf<2, true, false>,
                         cudaFuncAttributeMaxDynamicSharedMemorySize, op_smem);
    gemm_bf<2, true, false><<<dim3(8, 8, BATCH), 256, op_smem>>>(
        wo, att, b_out, x, d_out, CCH);
}

// round 14
// speedup vs baseline: 1.1925x; 1.0351x over previous
#include <cuda_runtime.h>
#include <cuda_bf16.h>
#include <math.h>
#include <stdint.h>

#define BATCH 16
#define CCH 512
#define HW 1024
#define HEADS 8
#define HD 64
#define GROUPS 8
#define CPG 64
#define CEXP 0.1803368801111244f    // 0.125 * log2(e)

// Scratch (no allocations allowed). All intermediates bf16.
__device__ __nv_bfloat16 g_xn[BATCH * CCH * HW];
__device__ __nv_bfloat16 g_qkv[BATCH * 3 * CCH * HW];
__device__ __nv_bfloat16 g_att[BATCH * CCH * HW];
__device__ __nv_bfloat16 g_wq[3 * CCH * CCH];
__device__ __nv_bfloat16 g_wo[CCH * CCH];

// ---------------------------------------------------------------------------
// helpers
// ---------------------------------------------------------------------------
__device__ __forceinline__ uint32_t pack_bf16(float lo, float hi) {
    uint32_t r;
    asm("cvt.rn.bf16x2.f32 %0, %1, %2;" : "=r"(r) : "f"(hi), "f"(lo));
    return r;
}

__device__ __forceinline__ uint32_t ex2_bf16x2(uint32_t x) {
    uint32_t y;
    asm("ex2.approx.ftz.bf16x2 %0, %1;" : "=r"(y) : "r"(x));
    return y;
}

__device__ __forceinline__ void mma_bf16(float* d, const uint32_t* a, const uint32_t* b) {
    asm volatile(
        "mma.sync.aligned.m16n8k16.row.col.f32.bf16.bf16.f32 "
        "{%0,%1,%2,%3}, {%4,%5,%6,%7}, {%8,%9}, {%0,%1,%2,%3};\n"
        : "+f"(d[0]), "+f"(d[1]), "+f"(d[2]), "+f"(d[3])
        : "r"(a[0]), "r"(a[1]), "r"(a[2]), "r"(a[3]), "r"(b[0]), "r"(b[1]));
}

__device__ __forceinline__ void ldsm4(uint32_t* r, uint32_t addr) {
    asm volatile("ldmatrix.sync.aligned.m8n8.x4.shared.b16 {%0,%1,%2,%3}, [%4];"
                 : "=r"(r[0]), "=r"(r[1]), "=r"(r[2]), "=r"(r[3]) : "r"(addr));
}
__device__ __forceinline__ void ldsm4t(uint32_t* r, uint32_t addr) {
    asm volatile("ldmatrix.sync.aligned.m8n8.x4.trans.shared.b16 {%0,%1,%2,%3}, [%4];"
                 : "=r"(r[0]), "=r"(r[1]), "=r"(r[2]), "=r"(r[3]) : "r"(addr));
}

__device__ __forceinline__ void cp16(uint32_t saddr, const void* gptr) {
    asm volatile("cp.async.cg.shared.global [%0], [%1], 16;\n" :: "r"(saddr), "l"(gptr));
}
#define CP_COMMIT()  asm volatile("cp.async.commit_group;\n" ::: "memory")
#define CP_WAIT0()   asm volatile("cp.async.wait_group 0;\n" ::: "memory")
#define CP_WAIT1()   asm volatile("cp.async.wait_group 1;\n" ::: "memory")

// ---------------------------------------------------------------------------
// Kernel 1: fused GroupNorm (blocks 0..127, 512 thr, shuffle reductions)
//           + weight bf16 convert (blocks 128..191).
// ---------------------------------------------------------------------------
__global__ __launch_bounds__(512) void gn_prep_kernel(
    const float* __restrict__ x, const float* __restrict__ gamma,
    const float* __restrict__ beta,
    const float* __restrict__ wq, const float* __restrict__ wo) {
    const int t = threadIdx.x;
    if (blockIdx.x >= BATCH * GROUPS) {
        int i = (blockIdx.x - BATCH * GROUPS) * 512 + t;
        int stride = 64 * 512;
        int nq = 3 * CCH * CCH / 4;
        for (int k = i; k < nq; k += stride) {
            float4 v = ((const float4*)wq)[k];
            ((uint2*)g_wq)[k] = make_uint2(pack_bf16(v.x, v.y), pack_bf16(v.z, v.w));
        }
        int no = CCH * CCH / 4;
        for (int k = i; k < no; k += stride) {
            float4 v = ((const float4*)wo)[k];
            ((uint2*)g_wo)[k] = make_uint2(pack_bf16(v.x, v.y), pack_bf16(v.z, v.w));
        }
        return;
    }
    const int b = blockIdx.x / GROUPS, g = blockIdx.x % GROUPS;
    const int lane = t & 31, wid = t >> 5;
    const float* xp = x + ((size_t)b * CCH + (size_t)g * CPG) * HW;
    __nv_bfloat16* op = g_xn + ((size_t)b * CCH + (size_t)g * CPG) * HW;
    const int n = CPG * HW;   // 65536

    float s = 0.f, sq = 0.f;
    for (int i = t * 4; i < n; i += 2048) {
        float4 v = *(const float4*)(xp + i);
        s  += v.x + v.y + v.z + v.w;
        sq += v.x * v.x + v.y * v.y + v.z * v.z + v.w * v.w;
    }
    #pragma unroll
    for (int off = 16; off > 0; off >>= 1) {
        s  += __shfl_xor_sync(0xffffffffu, s, off);
        sq += __shfl_xor_sync(0xffffffffu, sq, off);
    }
    __shared__ float rs[16], rq[16];
    __shared__ float s_mean, s_inv;
    if (lane == 0) { rs[wid] = s; rq[wid] = sq; }
    __syncthreads();
    if (wid == 0) {
        s  = (lane < 16) ? rs[lane] : 0.f;
        sq = (lane < 16) ? rq[lane] : 0.f;
        #pragma unroll
        for (int off = 8; off > 0; off >>= 1) {
            s  += __shfl_xor_sync(0xffffffffu, s, off);
            sq += __shfl_xor_sync(0xffffffffu, sq, off);
        }
        if (lane == 0) {
            float mean = s / (float)n;
            float var  = sq / (float)n - mean * mean;
            s_mean = mean;
            s_inv  = rsqrtf(var + 1e-5f);
        }
    }
    __syncthreads();
    const float mean = s_mean, inv = s_inv;
    for (int i = t * 4; i < n; i += 2048) {
        int ch = g * CPG + (i >> 10);
        float ga = gamma[ch] * inv;
        float be = beta[ch];
        float4 v = *(const float4*)(xp + i);
        uint2 p = make_uint2(
            pack_bf16((v.x - mean) * ga + be, (v.y - mean) * ga + be),
            pack_bf16((v.z - mean) * ga + be, (v.w - mean) * ga + be));
        *(uint2*)(op + i) = p;
    }
}

// ---------------------------------------------------------------------------
// Kernel 2/4: bf16 tensor-core batched GEMM. K=512 fixed -> 8 fully-unrolled
//   BK=64 iterations. NSTG-stage ring (compile-time indices), prefetch depth
//   NSTG-1. OCC = min CTAs/SM for launch bounds (register budget control).
// ---------------------------------------------------------------------------
#define GAS 72
#define GBS 136

template <int MT, int NSTG, int OCC, bool RESID, bool SCALEK>
__global__ __launch_bounds__(256, OCC) void gemm_bf(
    const __nv_bfloat16* __restrict__ W, const __nv_bfloat16* __restrict__ Xall,
    const float* __restrict__ bias, const float* __restrict__ resid,
    void* __restrict__ outAll, int M) {
    const int N = HW;
    const int K = CCH;                    // 512, fixed
    const int MROWS = 32 * MT;
    const int AS = MROWS * GAS;
    const int BS = 64 * GBS;
    const int bz = blockIdx.z;
    const __nv_bfloat16* X = Xall + (size_t)bz * K * N;
    const float* R = RESID ? (resid + (size_t)bz * M * N) : nullptr;

    extern __shared__ __nv_bfloat16 smg[];
    uint32_t base = (uint32_t)__cvta_generic_to_shared(smg);

    const int t = threadIdx.x;
    const int lane = t & 31, w = t >> 5;
    const int g = lane >> 2, t4 = lane & 3;
    const int l7 = lane & 7, b1 = (lane >> 3) & 1, b2 = (lane >> 4) & 1;
    const int wm = (w >> 2) * 16 * MT, wn = (w & 3) * 32;
    const int m0 = blockIdx.x * MROWS, n0 = blockIdx.y * 128;

    auto issue = [&](int k0, int st) {
        uint32_t sa = base + st * (AS + BS) * 2;
        uint32_t sb = sa + AS * 2;
        #pragma unroll
        for (int r = 0; r < MT; r++) {
            int c = t + r * 256;
            int row = c >> 3, cc = c & 7;
            cp16(sa + (row * GAS + cc * 8) * 2,
                 W + (size_t)(m0 + row) * K + k0 + cc * 8);
        }
        #pragma unroll
        for (int r = 0; r < 4; r++) {
            int c = t + r * 256;
            int row = c >> 4, cc = c & 15;
            cp16(sb + (row * GBS + cc * 8) * 2,
                 X + (size_t)(k0 + row) * N + n0 + cc * 8);
        }
        CP_COMMIT();
    };

    float acc[MT][4][4];
    #pragma unroll
    for (int i = 0; i < MT; i++)
        #pragma unroll
        for (int j = 0; j < 4; j++)
            #pragma unroll
            for (int r = 0; r < 4; r++) acc[i][j][r] = 0.f;

    issue(0, 0);
    if (NSTG == 3) issue(64, 1);

    const int aoff = (b1 * 8 + l7) * GAS + b2 * 8;
    const int boff = (b1 * 8 + l7) * GBS + b2 * 8;

    #pragma unroll
    for (int it = 0; it < 8; it++) {
        if (NSTG == 2 || it == 7) { CP_WAIT0(); } else { CP_WAIT1(); }
        __syncthreads();
        if (it + NSTG - 1 < 8) issue((it + NSTG - 1) * 64, (it + NSTG - 1) % NSTG);
        const int st = it % NSTG;                    // compile-time (full unroll)
        uint32_t sa = base + st * (AS + BS) * 2;
        uint32_t sb = sa + AS * 2;

        #pragma unroll
        for (int s = 0; s < 4; s++) {
            uint32_t af[MT][4], bf[2][4];
            #pragma unroll
            for (int mt = 0; mt < MT; mt++)
                ldsm4(af[mt], sa + ((wm + 16 * mt) * GAS + s * 16 + aoff) * 2);
            #pragma unroll
            for (int ntp = 0; ntp < 2; ntp++)
                ldsm4t(bf[ntp], sb + (s * 16 * GBS + wn + 16 * ntp + boff) * 2);
            #pragma unroll
            for (int mt = 0; mt < MT; mt++)
                #pragma unroll
                for (int nt = 0; nt < 4; nt++)
                    mma_bf16(acc[mt][nt], af[mt], &bf[nt >> 1][(nt & 1) * 2]);
        }
    }

    const float kscale = (SCALEK && m0 >= CCH && m0 < 2 * CCH) ? CEXP : 1.0f;
    #pragma unroll
    for (int mt = 0; mt < MT; mt++) {
        int ma = m0 + wm + 16 * mt + g;
        int mb = ma + 8;
        float ba = __ldg(&bias[ma]), bb = __ldg(&bias[mb]);
        #pragma unroll
        for (int nt = 0; nt < 4; nt++) {
            int n = n0 + wn + 8 * nt + 2 * t4;
            float v0 = acc[mt][nt][0] + ba, v1 = acc[mt][nt][1] + ba;
            float v2 = acc[mt][nt][2] + bb, v3 = acc[mt][nt][3] + bb;
            if (RESID) {
                float* out = (float*)outAll + (size_t)bz * M * N;
                float2 ra = *(const float2*)&R[(size_t)ma * N + n];
                float2 rb = *(const float2*)&R[(size_t)mb * N + n];
                *(float2*)&out[(size_t)ma * N + n] = make_float2(v0 + ra.x, v1 + ra.y);
                *(float2*)&out[(size_t)mb * N + n] = make_float2(v2 + rb.x, v3 + rb.y);
            } else {
                if (SCALEK) { v0 *= kscale; v1 *= kscale; v2 *= kscale; v3 *= kscale; }
                __nv_bfloat16* out = (__nv_bfloat16*)outAll + (size_t)bz * M * N;
                *(uint32_t*)&out[(size_t)ma * N + n] = pack_bf16(v0, v1);
                *(uint32_t*)&out[(size_t)mb * N + n] = pack_bf16(v2, v3);
            }
        }
    }
}

// ---------------------------------------------------------------------------
// Kernel 3: bf16 flash attention (round-13 proven, unchanged).
//   4-stage KV ring, prefetch depth 2, P = 2^s via ex2.bf16x2, l via ones-MMA.
// ---------------------------------------------------------------------------
#define BQ 128
#define AQS 136
#define AKS 72
#define OFF_K 8704                       // after Q (64*136)
#define OFF_V (8704 + 4 * 4608)          // 27136
#define ATT_ELTS (27136 + 4 * 4608)      // 45568 bf16 = 91136 B

__global__ __launch_bounds__(256, 2) void attn_bf() {
    extern __shared__ __nv_bfloat16 smb[];
    uint32_t base = (uint32_t)__cvta_generic_to_shared(smb);

    const int t = threadIdx.x;
    const int lane = t & 31, w = t >> 5;
    const int g = lane >> 2, t4 = lane & 3;
    const int l7 = lane & 7, b1 = (lane >> 3) & 1, b2 = (lane >> 4) & 1;
    const int q2 = lane >> 3;
    const int iw = w * 16;
    const int bh = blockIdx.y;
    const int b = bh >> 3, h = bh & 7;
    const int i0g = blockIdx.x * BQ;

    const __nv_bfloat16* qb = g_qkv + ((size_t)b * 3 * CCH + (size_t)h * HD) * HW;
    const __nv_bfloat16* kb = qb + (size_t)CCH * HW;
    const __nv_bfloat16* vb = qb + (size_t)2 * CCH * HW;

    #pragma unroll
    for (int r = 0; r < 4; r++) {
        int c = t + r * 256;
        int row = c >> 4, cc = c & 15;
        cp16(base + (row * AQS + cc * 8) * 2, qb + (size_t)row * HW + i0g + cc * 8);
    }

    auto issueKV = [&](int j0, int st) {
        uint32_t ks = base + (OFF_K + st * 4608) * 2;
        uint32_t vs = base + (OFF_V + st * 4608) * 2;
        #pragma unroll
        for (int r = 0; r < 2; r++) {
            int c = t + r * 256;
            int row = c >> 3, cc = c & 7;
            cp16(ks + (row * AKS + cc * 8) * 2, kb + (size_t)row * HW + j0 + cc * 8);
            cp16(vs + (row * AKS + cc * 8) * 2, vb + (size_t)row * HW + j0 + cc * 8);
        }
        CP_COMMIT();
    };
    issueKV(0, 0);    // includes Q chunks
    issueKV(64, 1);

    float o[8][4];
    #pragma unroll
    for (int dt = 0; dt < 8; dt++)
        #pragma unroll
        for (int r = 0; r < 4; r++) o[dt][r] = 0.f;
    float lacc[4] = {0.f, 0.f, 0.f, 0.f};
    const uint32_t onesb[2] = {0x3F803F80u, 0x3F803F80u};

    uint32_t qf[4][4];
    const int qoff = (b2 * 8 + l7) * AQS + iw + b1 * 8;
    const int koff = (b1 * 8 + l7) * AKS + b2 * 8;
    const int voff = l7 * AKS + q2 * 8;

    #pragma unroll 4
    for (int jt = 0; jt < 16; jt++) {
        if (jt == 15) { CP_WAIT0(); } else { CP_WAIT1(); }
        __syncthreads();
        if (jt + 2 < 16) issueKV((jt + 2) * 64, (jt + 2) & 3);

        if (jt == 0) {
            #pragma unroll
            for (int u = 0; u < 4; u++)
                ldsm4t(qf[u], base + (u * 16 * AQS + qoff) * 2);
        }
        uint32_t ksb = base + (OFF_K + (jt & 3) * 4608) * 2;
        uint32_t vsb = base + (OFF_V + (jt & 3) * 4608) * 2;

        // ---- S = Q K' ----
        float s[8][4];
        #pragma unroll
        for (int nt = 0; nt < 8; nt++)
            #pragma unroll
            for (int r = 0; r < 4; r++) s[nt][r] = 0.f;

        #pragma unroll
        for (int u = 0; u < 4; u++) {
            uint32_t kf[4][4];
            #pragma unroll
            for (int ntp = 0; ntp < 4; ntp++)
                ldsm4t(kf[ntp], ksb + (u * 16 * AKS + 16 * ntp + koff) * 2);
            #pragma unroll
            for (int nt = 0; nt < 8; nt++)
                mma_bf16(s[nt], qf[u], &kf[nt >> 1][(nt & 1) * 2]);
        }

        // ---- P = 2^s ----
        uint32_t pa[4][4];
        #pragma unroll
        for (int nt = 0; nt < 8; nt++) {
            pa[nt >> 1][(nt & 1) * 2]     = ex2_bf16x2(pack_bf16(s[nt][0], s[nt][1]));
            pa[nt >> 1][(nt & 1) * 2 + 1] = ex2_bf16x2(pack_bf16(s[nt][2], s[nt][3]));
        }

        // ---- l += P * ones ----
        #pragma unroll
        for (int u = 0; u < 4; u++)
            mma_bf16(lacc, pa[u], onesb);

        // ---- O += P V^T ----
        #pragma unroll
        for (int up = 0; up < 2; up++) {
            #pragma unroll
            for (int dt = 0; dt < 8; dt++) {
                uint32_t vf[4];
                ldsm4(vf, vsb + (dt * 8 * AKS + up * 32 + voff) * 2);
                mma_bf16(o[dt], pa[2 * up],     &vf[0]);
                mma_bf16(o[dt], pa[2 * up + 1], &vf[2]);
            }
        }
    }

    float inv_lo = 1.0f / lacc[0], inv_hi = 1.0f / lacc[2];

    __nv_bfloat16* ob = g_att + ((size_t)b * CCH + (size_t)h * HD) * HW;
    const int i_lo = i0g + iw + g, i_hi = i_lo + 8;
    #pragma unroll
    for (int dt = 0; dt < 8; dt++) {
        int d = dt * 8 + 2 * t4;
        ob[(size_t)d * HW + i_lo]       = __float2bfloat16_rn(o[dt][0] * inv_lo);
        ob[(size_t)(d + 1) * HW + i_lo] = __float2bfloat16_rn(o[dt][1] * inv_lo);
        ob[(size_t)d * HW + i_hi]       = __float2bfloat16_rn(o[dt][2] * inv_hi);
        ob[(size_t)(d + 1) * HW + i_hi] = __float2bfloat16_rn(o[dt][3] * inv_hi);
    }
}

// ---------------------------------------------------------------------------

extern "C" void kernel_launch(void* const* d_in, const int* in_sizes, int n_in,
                              void* d_out, int out_size) {
    const float* x     = (const float*)d_in[0];
    const float* gamma = (const float*)d_in[1];
    const float* beta  = (const float*)d_in[2];
    const float* w_qkv = (const float*)d_in[3];
    const float* b_qkv = (const float*)d_in[4];
    const float* w_out = (const float*)d_in[5];
    const float* b_out = (const float*)d_in[6];

    __nv_bfloat16 *xn, *qkv, *att, *wq, *wo;
    cudaGetSymbolAddress((void**)&xn,  g_xn);
    cudaGetSymbolAddress((void**)&qkv, g_qkv);
    cudaGetSymbolAddress((void**)&att, g_att);
    cudaGetSymbolAddress((void**)&wq,  g_wq);
    cudaGetSymbolAddress((void**)&wo,  g_wo);

    // 1) fused GroupNorm (512-thr, shuffle reduce) + weight conversion
    gn_prep_kernel<<<BATCH * GROUPS + 64, 512>>>(x, gamma, beta, w_qkv, w_out);

    // 2) QKV projection: MT=4, 3-stage ring, 2 CTAs/SM. smem 107520 B.
    const int qkv_smem = 3 * (128 * GAS + 64 * GBS) * 2;
    cudaFuncSetAttribute((const void*)gemm_bf<4, 3, 2, false, true>,
                         cudaFuncAttributeMaxDynamicSharedMemorySize, qkv_smem);
    gemm_bf<4, 3, 2, false, true><<<dim3(12, 8, BATCH), 256, qkv_smem>>>(
        wq, xn, b_qkv, nullptr, qkv, 3 * CCH);

    // 3) Attention: 4-stage KV ring. smem 91136 B.
    const int attn_smem = ATT_ELTS * 2;
    cudaFuncSetAttribute(attn_bf, cudaFuncAttributeMaxDynamicSharedMemorySize,
                         attn_smem);
    attn_bf<<<dim3(HW / BQ, BATCH * HEADS), 256, attn_smem>>>();

    // 4) Output projection + residual: MT=2, 2-stage ring, 3 CTAs/SM.
    //    smem 53248 B (x3 = 160 KB/SM).
    const int op_smem = 2 * (64 * GAS + 64 * GBS) * 2;
    cudaFuncSetAttribute((const void*)gemm_bf<2, 2, 3, true, false>,
                         cudaFuncAttributeMaxDynamicSharedMemorySize, op_smem);
    gemm_bf<2, 2, 3, true, false><<<dim3(8, 8, BATCH), 256, op_smem>>>(
        wo, att, b_out, x, d_out, CCH);
}